// round 9
// baseline (speedup 1.0000x reference)
#include <cuda_runtime.h>
#include <cuda_bf16.h>

#define N_VERTS 262144
#define N_PAIRS 8388608
#define NW      52429        // ceil(N_VERTS/5) packed words, 6 bits/vertex
#define NWPAD   52432        // padded to /4 for int4 staging
#define DHAT2   0.0025f
#define EPSF    1e-12f
// Conservative threshold in cell^2 units (cell = 0.125): true bound 3.76;
// use 61/16 = 3.8125. Tests: 16*ap2<61, 16*bp2<61, 16*cr^2<61*den.

__device__ float2   g_coords[N_VERTS];   // 2 MB, L2-resident
__device__ unsigned g_qtab[NWPAD];       // 6-bit quantized coords, 5/word

// Compaction scratch (worst case: all pairs pass).
__device__ int g_count;
__device__ int g_cv[N_PAIRS];
__device__ int g_ca[N_PAIRS];
__device__ int g_cb[N_PAIRS];

// ---------------------------------------------------------------- setup
__global__ void setup_kernel(const float* __restrict__ Uu,
                             const float* __restrict__ rest,
                             float* __restrict__ out) {
    int w = blockIdx.x * blockDim.x + threadIdx.x;
    if (w >= NWPAD) return;
    const float2* Uu2   = reinterpret_cast<const float2*>(Uu);
    const float2* rest2 = reinterpret_cast<const float2*>(rest);
    unsigned packed = 0;
    int base = w * 5;
    #pragma unroll
    for (int k = 0; k < 5; k++) {
        int vi = base + k;
        if (vi < N_VERTS) {
            float2 u = __ldg(&Uu2[vi]);
            float2 r = __ldg(&rest2[vi]);
            float2 c = make_float2(u.x + r.x, u.y + r.y);
            g_coords[vi] = c;
            int qx = min(7, max(0, (int)(c.x * 8.0f)));
            int qy = min(7, max(0, (int)(c.y * 8.0f)));
            packed |= (unsigned)(qx | (qy << 3)) << (6 * k);
        }
    }
    g_qtab[w] = packed;
    if (w == 0) { *out = 0.0f; g_count = 0; }
}

// ---------------------------------------------------------------- helpers
__device__ __forceinline__ unsigned qcode(const unsigned* __restrict__ s, int v) {
    unsigned w = (unsigned)v / 5u;
    unsigned r = (unsigned)v - w * 5u;
    return (s[w] >> (r * 6u)) & 63u;
}

__device__ __forceinline__ bool cell_filter(unsigned cp, unsigned ca, unsigned cb) {
    int px = cp & 7, py = (int)(cp >> 3);
    int ax = ca & 7, ay = (int)(ca >> 3);
    int bx = cb & 7, by = (int)(cb >> 3);
    int abx = bx - ax, aby = by - ay;
    int apx = px - ax, apy = py - ay;
    int den = abx * abx + aby * aby;
    int num = apx * abx + apy * aby;
    int ap2 = apx * apx + apy * apy;
    int bp2 = ap2 - 2 * num + den;
    int cr  = apx * aby - apy * abx;
    bool pass_a = (16 * ap2) < 61;
    bool pass_b = (16 * bp2) < 61;
    bool pass_m = (16 * cr * cr) < (61 * den);
    return (num <= 0) ? pass_a : (num >= den) ? pass_b : pass_m;
}

// ---------------------------------------------------------------- phase 1
// Filter + warp-aggregated compaction. Reg-light, 1024 threads, 1 CTA/SM.
extern __shared__ unsigned s_qtab[];     // NWPAD words (~205 KB)

#define BLK1 1024
#define GRID1 152

__global__ void __launch_bounds__(BLK1, 1)
filter_compact_kernel(const int4* __restrict__ pv,
                      const int4* __restrict__ pe0,
                      const int4* __restrict__ pe1) {
    {
        const int4* src = reinterpret_cast<const int4*>(g_qtab);
        int4*       dst = reinterpret_cast<int4*>(s_qtab);
        for (int i = threadIdx.x; i < NWPAD / 4; i += blockDim.x)
            dst[i] = __ldg(&src[i]);
    }
    __syncthreads();

    const int nq = N_PAIRS / 4;
    const int stride = gridDim.x * blockDim.x;
    const int gtid = blockIdx.x * blockDim.x + threadIdx.x;
    const int trips = (nq + stride - 1) / stride;   // uniform across warp
    const int lane = threadIdx.x & 31;
    const unsigned lt_mask = (1u << lane) - 1u;

    int q = gtid;
    bool ok = q < nq;
    int4 v, e0, e1;
    if (ok) { v = __ldcs(&pv[q]); e0 = __ldcs(&pe0[q]); e1 = __ldcs(&pe1[q]); }

    for (int it = 0; it < trips; ++it) {
        // prefetch next iteration's indices
        int qn = q + stride;
        bool okn = (it + 1 < trips) && (qn < nq);
        int4 vn, e0n, e1n;
        if (okn) { vn = __ldcs(&pv[qn]); e0n = __ldcs(&pe0[qn]); e1n = __ldcs(&pe1[qn]); }

        const int iv[4] = { v.x,  v.y,  v.z,  v.w  };
        const int ia[4] = { e0.x, e0.y, e0.z, e0.w };
        const int ib[4] = { e1.x, e1.y, e1.z, e1.w };

        bool pass[4];
        #pragma unroll
        for (int k = 0; k < 4; k++) {
            bool p = false;
            if (ok) {
                unsigned cp = qcode(s_qtab, iv[k]);
                unsigned ca = qcode(s_qtab, ia[k]);
                unsigned cb = qcode(s_qtab, ib[k]);
                p = cell_filter(cp, ca, cb);
            }
            pass[k] = p;
        }

        // warp-aggregated append per sub-slot
        #pragma unroll
        for (int k = 0; k < 4; k++) {
            unsigned bal = __ballot_sync(0xFFFFFFFFu, pass[k]);
            if (bal) {
                int cnt = __popc(bal);
                int base;
                if (lane == 0) base = atomicAdd(&g_count, cnt);
                base = __shfl_sync(0xFFFFFFFFu, base, 0);
                if (pass[k]) {
                    int off = base + __popc(bal & lt_mask);
                    g_cv[off] = iv[k];
                    g_ca[off] = ia[k];
                    g_cb[off] = ib[k];
                }
            }
        }

        v = vn; e0 = e0n; e1 = e1n; q = qn; ok = okn;
    }
}

// ---------------------------------------------------------------- phase 2
// Dense gather + exact barrier over the compacted list. No smem table.
#define BLK2 512
#define GRID2 608

__global__ void __launch_bounds__(BLK2)
gather_compute_kernel(float* __restrict__ out) {
    const int cnt = g_count;                    // uniform, set by phase 1
    const int T = gridDim.x * blockDim.x;
    const int gtid = blockIdx.x * blockDim.x + threadIdx.x;

    float acc = 0.0f;

    for (int base = gtid; base < cnt; base += 4 * T) {
        int qi[4];
        bool ok[4];
        #pragma unroll
        for (int j = 0; j < 4; j++) {
            qi[j] = base + j * T;
            ok[j] = qi[j] < cnt;
        }

        // 12 independent index loads (dense, coalesced)
        int iv[4], ia[4], ib[4];
        #pragma unroll
        for (int j = 0; j < 4; j++) {
            if (ok[j]) {
                iv[j] = __ldcs(&g_cv[qi[j]]);
                ia[j] = __ldcs(&g_ca[qi[j]]);
                ib[j] = __ldcs(&g_cb[qi[j]]);
            }
        }

        // 12 independent gathers (L2-resident coords)
        float2 P[4], A[4], B[4];
        #pragma unroll
        for (int j = 0; j < 4; j++) {
            P[j] = A[j] = B[j] = make_float2(0.0f, 0.0f);
            if (ok[j]) {
                P[j] = __ldg(&g_coords[iv[j]]);
                A[j] = __ldg(&g_coords[ia[j]]);
                B[j] = __ldg(&g_coords[ib[j]]);
            }
        }

        // exact barrier, gated by (slot valid && d2 < dhat2)
        #pragma unroll
        for (int j = 0; j < 4; j++) {
            float abx = B[j].x - A[j].x, aby = B[j].y - A[j].y;
            float apx = P[j].x - A[j].x, apy = P[j].y - A[j].y;
            float denom = abx * abx + aby * aby;
            float t = __saturatef(__fdividef(apx * abx + apy * aby,
                                             fmaxf(denom, EPSF)));
            float dx = apx - t * abx, dy = apy - t * aby;
            float d2 = dx * dx + dy * dy;
            float d2s = fmaxf(d2, EPSF);
            float g = d2s - DHAT2;
            float term = -(g * g) * __logf(d2s * (1.0f / DHAT2));
            bool valid = ok[j] && (d2 < DHAT2);
            acc += valid ? term : 0.0f;
        }
    }

    // block reduction
    #pragma unroll
    for (int off = 16; off > 0; off >>= 1)
        acc += __shfl_down_sync(0xFFFFFFFFu, acc, off);

    __shared__ float warp_sums[BLK2 / 32];
    int lane = threadIdx.x & 31;
    int wid  = threadIdx.x >> 5;
    if (lane == 0) warp_sums[wid] = acc;
    __syncthreads();

    if (wid == 0) {
        float s = (lane < BLK2 / 32) ? warp_sums[lane] : 0.0f;
        #pragma unroll
        for (int off = 8; off > 0; off >>= 1)
            s += __shfl_down_sync(0xFFFFFFFFu, s, off);
        if (lane == 0) atomicAdd(out, s);
    }
}

// ---------------------------------------------------------------- launch
extern "C" void kernel_launch(void* const* d_in, const int* in_sizes, int n_in,
                              void* d_out, int out_size) {
    const float* Uu   = (const float*)d_in[0];
    const float* rest = (const float*)d_in[1];
    const int*   pv   = (const int*)d_in[2];
    const int*   pe0  = (const int*)d_in[3];
    const int*   pe1  = (const int*)d_in[4];
    float* out = (float*)d_out;

    setup_kernel<<<(NWPAD + 255) / 256, 256>>>(Uu, rest, out);

    const size_t smem_bytes = (size_t)NWPAD * sizeof(unsigned);   // ~205 KB
    cudaFuncSetAttribute(filter_compact_kernel,
                         cudaFuncAttributeMaxDynamicSharedMemorySize,
                         (int)smem_bytes);

    filter_compact_kernel<<<GRID1, BLK1, smem_bytes>>>(
        (const int4*)pv, (const int4*)pe0, (const int4*)pe1);

    gather_compute_kernel<<<GRID2, BLK2>>>(out);
}

// round 10
// speedup vs baseline: 3.2159x; 3.2159x over previous
#include <cuda_runtime.h>
#include <cuda_bf16.h>

#define N_VERTS 262144
#define N_PAIRS 8388608
#define NW      52429        // ceil(N_VERTS/5) packed words, 6 bits/vertex
#define NWPAD   52432        // padded to /4 for int4 staging
#define DHAT2   0.0025f
#define EPSF    1e-12f
// Conservative threshold in cell^2 units (cell = 0.125): true bound 3.76;
// use 61/16 = 3.8125. Tests: 16*ap2<61, 16*bp2<61, 16*cr^2<61*den.

#define GRID1     152
#define BLK1      1024
#define TRIPS     14                     // ceil(2097152 / (152*1024))
#define SLICE_CAP (TRIPS * BLK1 * 4)     // 57344 pairs max per CTA slice

__device__ float2   g_coords[N_VERTS];   // 2 MB, L2-resident
__device__ unsigned g_qtab[NWPAD];       // 6-bit quantized coords, 5/word

// Per-CTA compaction slices: packed (iv | ia<<18 | ib<<36) u64 per pair.
__device__ unsigned long long g_cpk[GRID1 * SLICE_CAP];   // ~70 MB
__device__ int g_slice_cnt[GRID1];

// ---------------------------------------------------------------- setup
__global__ void setup_kernel(const float* __restrict__ Uu,
                             const float* __restrict__ rest,
                             float* __restrict__ out) {
    int w = blockIdx.x * blockDim.x + threadIdx.x;
    if (w < GRID1) g_slice_cnt[w] = 0;
    if (w >= NWPAD) return;
    const float2* Uu2   = reinterpret_cast<const float2*>(Uu);
    const float2* rest2 = reinterpret_cast<const float2*>(rest);
    unsigned packed = 0;
    int base = w * 5;
    #pragma unroll
    for (int k = 0; k < 5; k++) {
        int vi = base + k;
        if (vi < N_VERTS) {
            float2 u = __ldg(&Uu2[vi]);
            float2 r = __ldg(&rest2[vi]);
            float2 c = make_float2(u.x + r.x, u.y + r.y);
            g_coords[vi] = c;
            int qx = min(7, max(0, (int)(c.x * 8.0f)));
            int qy = min(7, max(0, (int)(c.y * 8.0f)));
            packed |= (unsigned)(qx | (qy << 3)) << (6 * k);
        }
    }
    g_qtab[w] = packed;
    if (w == 0) *out = 0.0f;
}

// ---------------------------------------------------------------- helpers
__device__ __forceinline__ unsigned qcode(const unsigned* __restrict__ s, int v) {
    unsigned w = (unsigned)v / 5u;
    unsigned r = (unsigned)v - w * 5u;
    return (s[w] >> (r * 6u)) & 63u;
}

__device__ __forceinline__ bool cell_filter(unsigned cp, unsigned ca, unsigned cb) {
    int px = cp & 7, py = (int)(cp >> 3);
    int ax = ca & 7, ay = (int)(ca >> 3);
    int bx = cb & 7, by = (int)(cb >> 3);
    int abx = bx - ax, aby = by - ay;
    int apx = px - ax, apy = py - ay;
    int den = abx * abx + aby * aby;
    int num = apx * abx + apy * aby;
    int ap2 = apx * apx + apy * apy;
    int bp2 = ap2 - 2 * num + den;
    int cr  = apx * aby - apy * abx;
    bool pass_a = (16 * ap2) < 61;
    bool pass_b = (16 * bp2) < 61;
    bool pass_m = (16 * cr * cr) < (61 * den);
    return (num <= 0) ? pass_a : (num >= den) ? pass_b : pass_m;
}

// ---------------------------------------------------------------- phase 1
// Filter + per-CTA compaction. NO global atomics in the loop: one smem
// atomic per warp-iteration, ballot-prefix lane offsets, coalesced stores.
extern __shared__ unsigned s_qtab[];     // NWPAD words (~205 KB)

__global__ void __launch_bounds__(BLK1, 1)
filter_compact_kernel(const int4* __restrict__ pv,
                      const int4* __restrict__ pe0,
                      const int4* __restrict__ pe1) {
    __shared__ int s_cnt;
    if (threadIdx.x == 0) s_cnt = 0;
    {
        const int4* src = reinterpret_cast<const int4*>(g_qtab);
        int4*       dst = reinterpret_cast<int4*>(s_qtab);
        for (int i = threadIdx.x; i < NWPAD / 4; i += blockDim.x)
            dst[i] = __ldg(&src[i]);
    }
    __syncthreads();

    const int nq = N_PAIRS / 4;
    const int stride = GRID1 * BLK1;
    const int lane = threadIdx.x & 31;
    const unsigned lt_mask = (1u << lane) - 1u;
    unsigned long long* slice = g_cpk + (size_t)blockIdx.x * SLICE_CAP;

    int q = blockIdx.x * BLK1 + threadIdx.x;
    bool ok = q < nq;
    int4 v, e0, e1;
    if (ok) { v = __ldcs(&pv[q]); e0 = __ldcs(&pe0[q]); e1 = __ldcs(&pe1[q]); }

    for (int it = 0; it < TRIPS; ++it) {
        // prefetch next iteration's indices
        int qn = q + stride;
        bool okn = (it + 1 < TRIPS) && (qn < nq);
        int4 vn, e0n, e1n;
        if (okn) { vn = __ldcs(&pv[qn]); e0n = __ldcs(&pe0[qn]); e1n = __ldcs(&pe1[qn]); }

        const int iv[4] = { v.x,  v.y,  v.z,  v.w  };
        const int ia[4] = { e0.x, e0.y, e0.z, e0.w };
        const int ib[4] = { e1.x, e1.y, e1.z, e1.w };

        bool pass[4];
        #pragma unroll
        for (int k = 0; k < 4; k++) {
            bool p = false;
            if (ok) {
                unsigned cp = qcode(s_qtab, iv[k]);
                unsigned ca = qcode(s_qtab, ia[k]);
                unsigned cb = qcode(s_qtab, ib[k]);
                p = cell_filter(cp, ca, cb);
            }
            pass[k] = p;
        }

        // one smem atomic per warp-iteration; ballot prefix for lane slots
        unsigned bal[4];
        #pragma unroll
        for (int k = 0; k < 4; k++)
            bal[k] = __ballot_sync(0xFFFFFFFFu, pass[k]);
        int tot = __popc(bal[0]) + __popc(bal[1]) + __popc(bal[2]) + __popc(bal[3]);

        int wbase = 0;
        if (lane == 0 && tot) wbase = atomicAdd(&s_cnt, tot);
        wbase = __shfl_sync(0xFFFFFFFFu, wbase, 0);

        int pre = 0;
        #pragma unroll
        for (int k = 0; k < 4; k++) {
            if (pass[k]) {
                int off = wbase + pre + __popc(bal[k] & lt_mask);
                unsigned long long pk = (unsigned long long)(unsigned)iv[k]
                                      | ((unsigned long long)(unsigned)ia[k] << 18)
                                      | ((unsigned long long)(unsigned)ib[k] << 36);
                slice[off] = pk;
            }
            pre += __popc(bal[k]);
        }

        v = vn; e0 = e0n; e1 = e1n; q = qn; ok = okn;
    }

    __syncthreads();
    if (threadIdx.x == 0) g_slice_cnt[blockIdx.x] = s_cnt;
}

// ---------------------------------------------------------------- phase 2
// Dense gather + exact barrier over per-CTA slices. No smem table ->
// high occupancy, 12 independent gathers in flight per thread.
#define BLK2 512

__global__ void __launch_bounds__(BLK2, 3)
gather_compute_kernel(float* __restrict__ out) {
    const int s  = blockIdx.x >> 2;          // slice
    const int qd = blockIdx.x & 3;           // quarter of the slice
    const int cnt = g_slice_cnt[s];
    const int lo = (cnt * qd) >> 2;
    const int hi = (cnt * (qd + 1)) >> 2;
    const unsigned long long* src = g_cpk + (size_t)s * SLICE_CAP;

    float acc = 0.0f;

    for (int base = lo + threadIdx.x; base < hi; base += 4 * BLK2) {
        bool ok[4];
        unsigned long long pk[4];
        #pragma unroll
        for (int j = 0; j < 4; j++) {
            int idx = base + j * BLK2;
            ok[j] = idx < hi;
            if (ok[j]) pk[j] = __ldcs(&src[idx]);
        }

        float2 P[4], A[4], B[4];
        #pragma unroll
        for (int j = 0; j < 4; j++) {
            P[j] = A[j] = B[j] = make_float2(0.0f, 0.0f);
            if (ok[j]) {
                int iv = (int)(pk[j] & 0x3FFFFu);
                int ia = (int)((pk[j] >> 18) & 0x3FFFFu);
                int ib = (int)((pk[j] >> 36) & 0x3FFFFu);
                P[j] = __ldg(&g_coords[iv]);
                A[j] = __ldg(&g_coords[ia]);
                B[j] = __ldg(&g_coords[ib]);
            }
        }

        #pragma unroll
        for (int j = 0; j < 4; j++) {
            float abx = B[j].x - A[j].x, aby = B[j].y - A[j].y;
            float apx = P[j].x - A[j].x, apy = P[j].y - A[j].y;
            float denom = abx * abx + aby * aby;
            float t = __saturatef(__fdividef(apx * abx + apy * aby,
                                             fmaxf(denom, EPSF)));
            float dx = apx - t * abx, dy = apy - t * aby;
            float d2 = dx * dx + dy * dy;
            float d2s = fmaxf(d2, EPSF);
            float g = d2s - DHAT2;
            float term = -(g * g) * __logf(d2s * (1.0f / DHAT2));
            bool valid = ok[j] && (d2 < DHAT2);
            acc += valid ? term : 0.0f;
        }
    }

    // block reduction
    #pragma unroll
    for (int off = 16; off > 0; off >>= 1)
        acc += __shfl_down_sync(0xFFFFFFFFu, acc, off);

    __shared__ float warp_sums[BLK2 / 32];
    int lane = threadIdx.x & 31;
    int wid  = threadIdx.x >> 5;
    if (lane == 0) warp_sums[wid] = acc;
    __syncthreads();

    if (wid == 0) {
        float sv = (lane < BLK2 / 32) ? warp_sums[lane] : 0.0f;
        #pragma unroll
        for (int off = 8; off > 0; off >>= 1)
            sv += __shfl_down_sync(0xFFFFFFFFu, sv, off);
        if (lane == 0) atomicAdd(out, sv);
    }
}

// ---------------------------------------------------------------- launch
extern "C" void kernel_launch(void* const* d_in, const int* in_sizes, int n_in,
                              void* d_out, int out_size) {
    const float* Uu   = (const float*)d_in[0];
    const float* rest = (const float*)d_in[1];
    const int*   pv   = (const int*)d_in[2];
    const int*   pe0  = (const int*)d_in[3];
    const int*   pe1  = (const int*)d_in[4];
    float* out = (float*)d_out;

    setup_kernel<<<(NWPAD + 255) / 256, 256>>>(Uu, rest, out);

    const size_t smem_bytes = (size_t)NWPAD * sizeof(unsigned);   // ~205 KB
    cudaFuncSetAttribute(filter_compact_kernel,
                         cudaFuncAttributeMaxDynamicSharedMemorySize,
                         (int)smem_bytes);

    filter_compact_kernel<<<GRID1, BLK1, smem_bytes>>>(
        (const int4*)pv, (const int4*)pe0, (const int4*)pe1);

    gather_compute_kernel<<<GRID1 * 4, BLK2>>>(out);
}